// round 10
// baseline (speedup 1.0000x reference)
#include <cuda_runtime.h>
#include <math.h>

// Nested-square smoothing-kernel weight, exactly as Python gen_kernel:
// ring index m = distance to nearest kernel edge; value = (m+1)/(center+1).
__device__ __forceinline__ float kernel_val(int i, int j, int lw, int center) {
    int m = min(min(i, j), min(lw - 1 - i, lw - 1 - j));
    return (float)((1.0 / (double)(center + 1)) * (double)(m + 1));
}

// Persistent grid-stride zero-fill with inline blob stamping.
// Each float4 store slot computes its own value: almost always (0,0,0,0);
// for the <=2*lw rows crossing a blob footprint, the owning thread computes
// the exact clipped conv value. No second pass, no ordering hazard.
__global__ void __launch_bounds__(256) RenderNet_fused_kernel(
    const float* __restrict__ x0, const float* __restrict__ y0,
    const float* __restrict__ x1, const float* __restrict__ y1,
    const int* __restrict__ p_x0, const int* __restrict__ p_y0,
    const int* __restrict__ p_x1, const int* __restrict__ p_y1,
    const int* __restrict__ p_nsteps, const int* __restrict__ p_steep,
    const int* __restrict__ p_lw,
    float* __restrict__ out, int imsize)
{
    // ---- scalar params: loaded once per block, amortized over ~165KB of
    // stores. All independent loads -> single latency exposure. ----
    const int steep = __ldg(p_steep);
    const int lw    = __ldg(p_lw);
    const int pad   = lw >> 1;
    const int r0 = steep ? __ldg(p_y0) : __ldg(p_x0); // img[0,0,r0,c0]
    const int c0 = steep ? __ldg(p_x0) : __ldg(p_y0);
    const int r1 = __ldg(p_x1);                        // img[1,0,_x1,_y1]
    const int c1 = __ldg(p_y1);

    // v = z * (1/z) in IEEE f32 RN, matching the jnp expression bit-exactly.
    const float za = __fadd_rn(__ldg(x0), __ldg(y0));
    const float v0 = __fmul_rn(za, __fdiv_rn(1.0f, za));
    const float zb = __fadd_rn(__ldg(x1), __ldg(y1));
    const float v1 = __fmul_rn(zb, __fdiv_rn(1.0f, zb));
    const float nf = (float)__ldg(p_nsteps);

    const unsigned w4     = (unsigned)imsize >> 2;       // float4 per row (pow2)
    const int      lshift = 31 - __clz((int)w4);         // log2(w4)
    const unsigned rmask  = (unsigned)imsize - 1u;
    const unsigned total4 = 3u * (unsigned)imsize * w4;  // total float4 slots

    float4* __restrict__ o4 = reinterpret_cast<float4*>(out);
    const float4 z4 = make_float4(0.f, 0.f, 0.f, 0.f);

    const unsigned stride = gridDim.x * blockDim.x;
    const unsigned tid0   = blockIdx.x * blockDim.x + threadIdx.x;

    for (unsigned base = tid0; base < total4; base += 4u * stride) {
        #pragma unroll
        for (int u = 0; u < 4; u++) {
            const unsigned i = base + (unsigned)u * stride;
            if (i >= total4) break;

            // row/col within the channel plane (imsize is a power of two).
            const unsigned row = (i >> lshift) & rmask;
            const bool in0 = (unsigned)((int)row - r0 + pad) < (unsigned)lw;
            const bool in1 = (unsigned)((int)row - r1 + pad) < (unsigned)lw;

            if (!(in0 || in1)) {            // overwhelmingly common path
                o4[i] = z4;
                continue;
            }

            const int cbase = (int)((i & (w4 - 1u)) << 2);
            const bool hit0 = in0 && (cbase + 3 >= c0 - pad) && (cbase <= c0 + pad);
            const bool hit1 = in1 && (cbase + 3 >= c1 - pad) && (cbase <= c1 + pad);
            if (!(hit0 || hit1)) {
                o4[i] = z4;
                continue;
            }

            float4 v = z4;
            float* vp = &v.x;
            #pragma unroll
            for (int e = 0; e < 4; e++) {
                const int c = cbase + e;
                float total = 0.0f;
                int di = (int)row - r0 + pad;
                int dj = c        - c0 + pad;
                if (in0 && (unsigned)dj < (unsigned)lw)
                    total = __fmul_rn(nf, __fmul_rn(kernel_val(di, dj, lw, pad), v0));
                di = (int)row - r1 + pad;
                dj = c        - c1 + pad;
                if (in1 && (unsigned)dj < (unsigned)lw)
                    total = __fadd_rn(total, __fmul_rn(kernel_val(di, dj, lw, pad), v1));
                vp[e] = fminf(fmaxf(total, 0.0f), 1.0f);
            }
            o4[i] = v;
        }
    }
}

extern "C" void kernel_launch(void* const* d_in, const int* in_sizes, int n_in,
                              void* d_out, int out_size)
{
    // Input order (metadata): x0, y0, x1, y1 (f32), _x0, _y0, _x1, _y1,
    // n_steps, steep, imsize, linewidth (i32).
    const float* x0 = (const float*)d_in[0];
    const float* y0 = (const float*)d_in[1];
    const float* x1 = (const float*)d_in[2];
    const float* y1 = (const float*)d_in[3];
    const int* p_x0     = (const int*)d_in[4];
    const int* p_y0     = (const int*)d_in[5];
    const int* p_x1     = (const int*)d_in[6];
    const int* p_y1     = (const int*)d_in[7];
    const int* p_nsteps = (const int*)d_in[8];
    const int* p_steep  = (const int*)d_in[9];
    const int* p_lw     = (const int*)d_in[11];

    float* out = (float*)d_out;

    // Output is (1, 3, imsize, imsize) f32 -> recover imsize on host.
    const int imsize = (int)(sqrt((double)out_size / 3.0) + 0.5);

    // Persistent-style grid: 8 blocks per SM on a 152-SM GB300.
    const int blocks = 152 * 8;
    RenderNet_fused_kernel<<<blocks, 256>>>(x0, y0, x1, y1,
                                            p_x0, p_y0, p_x1, p_y1,
                                            p_nsteps, p_steep, p_lw,
                                            out, imsize);
}

// round 12
// speedup vs baseline: 1.1343x; 1.1343x over previous
#include <cuda_runtime.h>
#include <math.h>

// Nested-square smoothing-kernel weight, exactly as Python gen_kernel:
// ring index m = distance to nearest kernel edge; value = (m+1)/(center+1).
__device__ __forceinline__ float kernel_val(int i, int j, int lw, int center) {
    int m = min(min(i, j), min(lw - 1 - i, lw - 1 - j));
    return (float)((1.0 / (double)(center + 1)) * (double)(m + 1));
}

// One block per image row, covering ALL 3 channels (48KB of stores/block).
// Fast path: 12 independent streaming STG.128 per thread. Then the (rare)
// patch overwrite: the 3 channels are an exact broadcast of one template, so
// the value is computed once and stored to all three planes by the same
// thread that wrote the zeros (program order => no sync needed).
__global__ void __launch_bounds__(256) RenderNet_fused_kernel(
    const float* __restrict__ x0, const float* __restrict__ y0,
    const float* __restrict__ x1, const float* __restrict__ y1,
    const int* __restrict__ p_x0, const int* __restrict__ p_y0,
    const int* __restrict__ p_x1, const int* __restrict__ p_y1,
    const int* __restrict__ p_nsteps, const int* __restrict__ p_steep,
    const int* __restrict__ p_lw,
    float* __restrict__ out, int imsize)
{
    const int row = blockIdx.x;
    const int t   = threadIdx.x;
    const unsigned w4 = (unsigned)imsize >> 2;           // float4 per row
    const size_t plane4 = (size_t)imsize * (size_t)w4;   // float4 per channel

    float4* __restrict__ o4 = reinterpret_cast<float4*>(out);
    float4* rp0 = o4 + (size_t)row * (size_t)w4;         // channel 0 row
    float4* rp1 = rp0 + plane4;                          // channel 1 row
    float4* rp2 = rp1 + plane4;                          // channel 2 row

    const float4 z4 = make_float4(0.f, 0.f, 0.f, 0.f);

    // Fast path: blast all 3 channel rows with streaming zeros.
    // imsize=4096 -> w4=1024 -> 4 slots/thread/channel = 12 independent
    // STG.128 with evict-first hint (write-only data; don't park in L2).
    if (w4 == 1024) {
        __stcs(rp0 + t,        z4); __stcs(rp0 + t + 256, z4);
        __stcs(rp0 + t + 512,  z4); __stcs(rp0 + t + 768, z4);
        __stcs(rp1 + t,        z4); __stcs(rp1 + t + 256, z4);
        __stcs(rp1 + t + 512,  z4); __stcs(rp1 + t + 768, z4);
        __stcs(rp2 + t,        z4); __stcs(rp2 + t + 256, z4);
        __stcs(rp2 + t + 512,  z4); __stcs(rp2 + t + 768, z4);
    } else {
        for (unsigned s = t; s < w4; s += 256) {
            __stcs(rp0 + s, z4);
            __stcs(rp1 + s, z4);
            __stcs(rp2 + s, z4);
        }
    }

    // Row-membership test (tiny scalar loads; overlap with the stores above;
    // L1-hit after the first block per SM).
    const int steep = __ldg(p_steep);
    const int lw    = __ldg(p_lw);
    const int pad   = lw >> 1;
    const int r0 = steep ? __ldg(p_y0) : __ldg(p_x0); // img[0,0,r0,c0]
    const int r1 = __ldg(p_x1);                        // img[1,0,_x1,_y1]
    const bool in0 = (unsigned)(row - r0 + pad) < (unsigned)lw;
    const bool in1 = (unsigned)(row - r1 + pad) < (unsigned)lw;
    if (!(in0 || in1)) return;

    // Slow path: this row crosses a blob footprint (<= 2*lw of 4096 rows).
    const int c0 = steep ? __ldg(p_x0) : __ldg(p_y0);
    const int c1 = __ldg(p_y1);

    // v = z * (1/z) in IEEE f32 RN, matching the jnp expression bit-exactly.
    const float za = __fadd_rn(__ldg(x0), __ldg(y0));
    const float v0 = __fmul_rn(za, __fdiv_rn(1.0f, za));
    const float zb = __fadd_rn(__ldg(x1), __ldg(y1));
    const float v1 = __fmul_rn(zb, __fdiv_rn(1.0f, zb));
    const float nf = (float)__ldg(p_nsteps);

    for (unsigned s = t; s < w4; s += 256) {
        const int cbase = (int)(s << 2);
        const bool hit0 = in0 && (cbase + 3 >= c0 - pad) && (cbase <= c0 + pad);
        const bool hit1 = in1 && (cbase + 3 >= c1 - pad) && (cbase <= c1 + pad);
        if (!(hit0 || hit1)) continue;

        float4 v = z4;
        float* vp = &v.x;
        #pragma unroll
        for (int e = 0; e < 4; e++) {
            const int c = cbase + e;
            float total = 0.0f;
            int di = row - r0 + pad;
            int dj = c   - c0 + pad;
            if (in0 && (unsigned)dj < (unsigned)lw)
                total = __fmul_rn(nf, __fmul_rn(kernel_val(di, dj, lw, pad), v0));
            di = row - r1 + pad;
            dj = c   - c1 + pad;
            if (in1 && (unsigned)dj < (unsigned)lw)
                total = __fadd_rn(total, __fmul_rn(kernel_val(di, dj, lw, pad), v1));
            vp[e] = fminf(fmaxf(total, 0.0f), 1.0f);
        }
        // Same template value on all 3 channels; same thread wrote the zeros.
        rp0[s] = v;
        rp1[s] = v;
        rp2[s] = v;
    }
}

extern "C" void kernel_launch(void* const* d_in, const int* in_sizes, int n_in,
                              void* d_out, int out_size)
{
    // Input order (metadata): x0, y0, x1, y1 (f32), _x0, _y0, _x1, _y1,
    // n_steps, steep, imsize, linewidth (i32).
    const float* x0 = (const float*)d_in[0];
    const float* y0 = (const float*)d_in[1];
    const float* x1 = (const float*)d_in[2];
    const float* y1 = (const float*)d_in[3];
    const int* p_x0     = (const int*)d_in[4];
    const int* p_y0     = (const int*)d_in[5];
    const int* p_x1     = (const int*)d_in[6];
    const int* p_y1     = (const int*)d_in[7];
    const int* p_nsteps = (const int*)d_in[8];
    const int* p_steep  = (const int*)d_in[9];
    const int* p_lw     = (const int*)d_in[11];

    float* out = (float*)d_out;

    // Output is (1, 3, imsize, imsize) f32 -> recover imsize on host.
    const int imsize = (int)(sqrt((double)out_size / 3.0) + 0.5);

    // One block per image row; each block writes all 3 channels of its row.
    RenderNet_fused_kernel<<<imsize, 256>>>(x0, y0, x1, y1,
                                            p_x0, p_y0, p_x1, p_y1,
                                            p_nsteps, p_steep, p_lw,
                                            out, imsize);
}